// round 1
// baseline (speedup 1.0000x reference)
#include <cuda_runtime.h>
#include <cstdint>

// ---------------- problem constants ----------------
#define BATCH 256
#define HW    147456           // 384*384
#define NB    4096             // histogram bins
#define PPB   1024             // pixels per block (256 thr * 4 px)
#define BPS   (HW / PPB)       // 144 blocks per sample
#define GRID  (BATCH * BPS)    // 36864
#define CAP   4096             // candidate capacity per quantile per sample

// target order-statistic ranks (0-based): q*(n-1) = 14745.5 / 132709.5
#define KL  14745
#define KL2 14746
#define KH  132709
#define KH2 132710

// ---------------- device scratch (static, allocation-free) ----------------
__device__ float g_xg[BATCH * HW];                 // channel-mean image, 151 MB
__device__ int   g_hist[BATCH * NB];               // per-sample histograms, 4 MB
__device__ int   g_sel[BATCH][6];                  // loBinMin, loBinMax, cumLo, hiBinMin, hiBinMax, cumHi
__device__ int   g_cntLo[BATCH];
__device__ int   g_cntHi[BATCH];
__device__ float g_candLo[BATCH * CAP];
__device__ float g_candHi[BATCH * CAP];
__device__ float g_lo[BATCH];
__device__ float g_inv[BATCH];

// ---------------- pass 0: zero scratch (graph-replay safe) ----------------
__global__ void zero_kernel() {
    int idx = blockIdx.x * blockDim.x + threadIdx.x;
    int stride = gridDim.x * blockDim.x;
    for (int i = idx; i < BATCH * NB; i += stride) g_hist[i] = 0;
    if (idx < BATCH) { g_cntLo[idx] = 0; g_cntHi[idx] = 0; }
}

__device__ __forceinline__ int bin_of(float m) {
    int b = (int)(m * (float)NB);
    return min(NB - 1, max(0, b));
}

// ---------------- pass A: xg = mean_c(x), write xg, histogram ----------------
__global__ void __launch_bounds__(256) passA(const float* __restrict__ x) {
    __shared__ int sh[NB];
    int s   = blockIdx.x / BPS;
    int blk = blockIdx.x % BPS;

    for (int i = threadIdx.x; i < NB; i += 256) sh[i] = 0;
    __syncthreads();

    int p = s * HW + blk * PPB + threadIdx.x * 4;      // global pixel index (mult of 4)
    const float4* xin = (const float4*)x;
    long long f4 = (long long)p * 3 / 4;
    float4 a = xin[f4 + 0];
    float4 b = xin[f4 + 1];
    float4 c = xin[f4 + 2];

    const float third = 1.0f / 3.0f;
    float m0 = (a.x + a.y + a.z) * third;
    float m1 = (a.w + b.x + b.y) * third;
    float m2 = (b.z + b.w + c.x) * third;
    float m3 = (c.y + c.z + c.w) * third;

    float4 out; out.x = m0; out.y = m1; out.z = m2; out.w = m3;
    ((float4*)g_xg)[p >> 2] = out;

    atomicAdd(&sh[bin_of(m0)], 1);
    atomicAdd(&sh[bin_of(m1)], 1);
    atomicAdd(&sh[bin_of(m2)], 1);
    atomicAdd(&sh[bin_of(m3)], 1);
    __syncthreads();

    int* gh = &g_hist[s * NB];
    for (int i = threadIdx.x; i < NB; i += 256) {
        int v = sh[i];
        if (v) atomicAdd(&gh[i], v);
    }
}

// ---------------- pass B: locate bins holding the 4 target ranks ----------------
__global__ void __launch_bounds__(256) passB() {
    int s = blockIdx.x;
    int t = threadIdx.x;
    const int CH = NB / 256;  // 16 bins per thread
    __shared__ int scan[256];

    int cnt[CH];
    int local = 0;
    const int* gh = &g_hist[s * NB];
    int base = t * CH;
#pragma unroll
    for (int i = 0; i < CH; i++) { cnt[i] = gh[base + i]; local += cnt[i]; }

    scan[t] = local;
    __syncthreads();
    // Hillis-Steele inclusive scan over 256
    for (int off = 1; off < 256; off <<= 1) {
        int v = (t >= off) ? scan[t - off] : 0;
        __syncthreads();
        scan[t] += v;
        __syncthreads();
    }
    int cum = scan[t] - local;   // exclusive prefix for this thread's chunk

    const int targets[4] = {KL, KL2, KH, KH2};
#pragma unroll
    for (int i = 0; i < CH; i++) {
        int c = cnt[i];
#pragma unroll
        for (int k = 0; k < 4; k++) {
            int r = targets[k];
            if (cum <= r && r < cum + c) {
                if (k == 0) { g_sel[s][0] = base + i; g_sel[s][2] = cum; }
                if (k == 1) { g_sel[s][1] = base + i; }
                if (k == 2) { g_sel[s][3] = base + i; g_sel[s][5] = cum; }
                if (k == 3) { g_sel[s][4] = base + i; }
            }
        }
        cum += c;
    }
}

// ---------------- pass C: gather candidate values from target bins ----------------
__global__ void __launch_bounds__(256) passC() {
    int s   = blockIdx.x / BPS;
    int blk = blockIdx.x % BPS;

    int loMin = g_sel[s][0], loMax = g_sel[s][1];
    int hiMin = g_sel[s][3], hiMax = g_sel[s][4];

    int p = blk * PPB + threadIdx.x * 4;   // local pixel within sample
    float4 v = ((const float4*)(g_xg + (long long)s * HW))[p >> 2];

    float m[4] = {v.x, v.y, v.z, v.w};
#pragma unroll
    for (int i = 0; i < 4; i++) {
        int b = bin_of(m[i]);
        if (b >= loMin && b <= loMax) {
            int idx = atomicAdd(&g_cntLo[s], 1);
            if (idx < CAP) g_candLo[s * CAP + idx] = m[i];
        }
        if (b >= hiMin && b <= hiMax) {
            int idx = atomicAdd(&g_cntHi[s], 1);
            if (idx < CAP) g_candHi[s * CAP + idx] = m[i];
        }
    }
}

// ---------------- pass D: exact selection among candidates ----------------
__global__ void __launch_bounds__(256) passD() {
    int s = blockIdx.x;
    __shared__ float sv[CAP];
    __shared__ float res[4];

    for (int q = 0; q < 2; q++) {
        const float* cand = q ? &g_candHi[s * CAP] : &g_candLo[s * CAP];
        int n = min(q ? g_cntHi[s] : g_cntLo[s], CAP);
        int cumBefore = g_sel[s][q ? 5 : 2];
        int t0 = (q ? KH : KL) - cumBefore;
        int t1 = t0 + 1;

        for (int i = threadIdx.x; i < n; i += 256) sv[i] = cand[i];
        __syncthreads();

        for (int i = threadIdx.x; i < n; i += 256) {
            float v = sv[i];
            int L = 0, E = 0;
            for (int j = 0; j < n; j++) {
                float u = sv[j];
                L += (u < v);
                E += (u == v);
            }
            if (L <= t0 && t0 < L + E) res[2 * q + 0] = v;
            if (L <= t1 && t1 < L + E) res[2 * q + 1] = v;
        }
        __syncthreads();
    }

    if (threadIdx.x == 0) {
        float lo = 0.5f * (res[0] + res[1]);
        float hi = 0.5f * (res[2] + res[3]);
        float rng = fmaxf(hi - lo, 1e-6f);
        g_lo[s]  = lo;
        g_inv[s] = 1.0f / rng;
    }
}

// ---------------- pass E: normalize + clip ----------------
__global__ void __launch_bounds__(256) passE(float* __restrict__ out) {
    int s   = blockIdx.x / BPS;
    int blk = blockIdx.x % BPS;
    float lo  = __ldg(&g_lo[s]);
    float inv = __ldg(&g_inv[s]);

    long long p = (long long)s * HW + blk * PPB + threadIdx.x * 4;
    float4 v = ((const float4*)g_xg)[p >> 2];
    float4 r;
    r.x = __saturatef((v.x - lo) * inv);
    r.y = __saturatef((v.y - lo) * inv);
    r.z = __saturatef((v.z - lo) * inv);
    r.w = __saturatef((v.w - lo) * inv);
    ((float4*)out)[p >> 2] = r;
}

// ---------------- launch ----------------
extern "C" void kernel_launch(void* const* d_in, const int* in_sizes, int n_in,
                              void* d_out, int out_size) {
    const float* x = (const float*)d_in[0];
    float* out = (float*)d_out;

    zero_kernel<<<4096, 256>>>();
    passA<<<GRID, 256>>>(x);
    passB<<<BATCH, 256>>>();
    passC<<<GRID, 256>>>();
    passD<<<BATCH, 256>>>();
    passE<<<GRID, 256>>>(out);
}

// round 2
// speedup vs baseline: 1.6661x; 1.6661x over previous
#include <cuda_runtime.h>
#include <cstdint>

// ---------------- problem constants ----------------
#define BATCH 256
#define HW    147456           // 384*384
#define NB    4096             // histogram bins
#define CAP   4096             // candidate capacity per quantile per sample

// target order-statistic ranks (0-based): q*(n-1) = 14745.5 / 132709.5
#define KL  14745
#define KL2 14746
#define KH  132709
#define KH2 132710

// passA geometry: 8 blocks/sample, 512 threads, 36 px/thread
#define TPB_A  512
#define BPS_A  8
#define PXB_A  (HW / BPS_A)        // 18432 px per block
#define ITER_A (PXB_A / (TPB_A*4)) // 9 iterations of 4 px

// passC/E geometry: 36 blocks/sample, 512 threads, 8 px/thread
#define TPB_C  512
#define BPS_C  36
#define PXB_C  (HW / BPS_C)        // 4096 px per block
#define ITER_C (PXB_C / (TPB_C*4)) // 2 iterations of 4 px

// ---------------- device scratch (static, allocation-free, zero-init) -------
__device__ float g_xg[BATCH * HW];        // channel-mean image, 151 MB
__device__ int   g_hist[BATCH * NB];      // per-sample histograms (self-cleaned)
__device__ float g_thr[BATCH][4];         // loT0, loT1, hiT0, hiT1 (in t = v*4096 units)
__device__ int   g_cum[BATCH][2];         // exclusive counts before lo/hi target ranges
__device__ int   g_cntLo[BATCH];          // candidate counters (self-cleaned)
__device__ int   g_cntHi[BATCH];
__device__ float g_candLo[BATCH * CAP];
__device__ float g_candHi[BATCH * CAP];
__device__ float g_lo[BATCH];
__device__ float g_inv[BATCH];

// ---------------- pass A: xg = mean_c(x), write xg, histogram ----------------
__global__ void __launch_bounds__(TPB_A) passA(const float* __restrict__ x) {
    __shared__ int sh[NB];
    int s     = blockIdx.x >> 3;       // /BPS_A
    int chunk = blockIdx.x & (BPS_A - 1);

    for (int i = threadIdx.x; i < NB; i += TPB_A) sh[i] = 0;
    __syncthreads();

    const int base = s * HW + chunk * PXB_A;
    const float4* __restrict__ xin = (const float4*)x;
    const float third = 1.0f / 3.0f;

#pragma unroll 3
    for (int it = 0; it < ITER_A; ++it) {
        int p  = base + it * (TPB_A * 4) + threadIdx.x * 4;  // global px, mult of 4
        int f4 = (p * 3) >> 2;
        float4 a = __ldcs(xin + f4 + 0);   // streaming: don't pollute L2
        float4 b = __ldcs(xin + f4 + 1);
        float4 c = __ldcs(xin + f4 + 2);

        float m0 = (a.x + a.y + a.z) * third;
        float m1 = (a.w + b.x + b.y) * third;
        float m2 = (b.z + b.w + c.x) * third;
        float m3 = (c.y + c.z + c.w) * third;

        float4 o; o.x = m0; o.y = m1; o.z = m2; o.w = m3;
        ((float4*)g_xg)[p >> 2] = o;       // default store: retain in L2

        atomicAdd(&sh[min((int)(m0 * (float)NB), NB - 1)], 1);
        atomicAdd(&sh[min((int)(m1 * (float)NB), NB - 1)], 1);
        atomicAdd(&sh[min((int)(m2 * (float)NB), NB - 1)], 1);
        atomicAdd(&sh[min((int)(m3 * (float)NB), NB - 1)], 1);
    }
    __syncthreads();

    int* gh = &g_hist[s * NB];
    for (int i = threadIdx.x; i < NB; i += TPB_A) {
        int v = sh[i];
        if (v) atomicAdd(&gh[i], v);   // no return use -> RED
    }
}

// ---------------- pass B: locate ranks, export value thresholds, zero hist ----
__global__ void __launch_bounds__(256) passB() {
    int s = blockIdx.x;
    int t = threadIdx.x;
    const int CH = NB / 256;  // 16 bins per thread
    __shared__ int scan[256];
    __shared__ int selBin[4];   // bins holding ranks KL, KL2, KH, KH2
    __shared__ int selCum[4];   // exclusive counts before those bins

    int cnt[CH];
    int local = 0;
    int* gh = &g_hist[s * NB];
    int base = t * CH;
#pragma unroll
    for (int i = 0; i < CH; i++) { cnt[i] = gh[base + i]; local += cnt[i]; }
    // self-clean for next graph replay (each thread zeroes exactly what it read)
#pragma unroll
    for (int i = 0; i < CH; i++) gh[base + i] = 0;

    scan[t] = local;
    __syncthreads();
    for (int off = 1; off < 256; off <<= 1) {
        int v = (t >= off) ? scan[t - off] : 0;
        __syncthreads();
        scan[t] += v;
        __syncthreads();
    }
    int cum = scan[t] - local;   // exclusive prefix for this thread's chunk

    const int targets[4] = {KL, KL2, KH, KH2};
#pragma unroll
    for (int i = 0; i < CH; i++) {
        int c = cnt[i];
#pragma unroll
        for (int k = 0; k < 4; k++) {
            int r = targets[k];
            if (cum <= r && r < cum + c) { selBin[k] = base + i; selCum[k] = cum; }
        }
        cum += c;
    }
    __syncthreads();

    if (t == 0) {
        int loMin = selBin[0], loMax = selBin[1];
        int hiMin = selBin[2], hiMax = selBin[3];
        // thresholds in t = v*NB units; value v is in bin b iff b <= v*NB < b+1
        g_thr[s][0] = (float)loMin;
        g_thr[s][1] = (loMax == NB - 1) ? 3.0e38f : (float)(loMax + 1);
        g_thr[s][2] = (float)hiMin;
        g_thr[s][3] = (hiMax == NB - 1) ? 3.0e38f : (float)(hiMax + 1);
        g_cum[s][0] = selCum[0];   // count strictly before loMin bin
        g_cum[s][1] = selCum[2];   // count strictly before hiMin bin
    }
}

// ---------------- pass C: gather candidates via float-threshold compares ------
__global__ void __launch_bounds__(TPB_C) passC() {
    int s     = blockIdx.x / BPS_C;
    int chunk = blockIdx.x % BPS_C;

    float l0 = g_thr[s][0], l1 = g_thr[s][1];
    float h0 = g_thr[s][2], h1 = g_thr[s][3];

    const float4* __restrict__ xg4 = (const float4*)(g_xg + s * HW);
    int base = chunk * PXB_C + threadIdx.x * 4;

#pragma unroll
    for (int it = 0; it < ITER_C; ++it) {
        float4 v = xg4[(base + it * (TPB_C * 4)) >> 2];
        float m[4] = {v.x, v.y, v.z, v.w};
#pragma unroll
        for (int i = 0; i < 4; i++) {
            float tt = m[i] * (float)NB;
            if (tt >= l0 && tt < l1) {
                int idx = atomicAdd(&g_cntLo[s], 1);
                if (idx < CAP) g_candLo[s * CAP + idx] = m[i];
            }
            if (tt >= h0 && tt < h1) {
                int idx = atomicAdd(&g_cntHi[s], 1);
                if (idx < CAP) g_candHi[s * CAP + idx] = m[i];
            }
        }
    }
}

// ---------------- pass D: exact selection among candidates -------------------
__global__ void __launch_bounds__(256) passD() {
    int s = blockIdx.x;
    __shared__ float sv[CAP];
    __shared__ float res[4];

    for (int q = 0; q < 2; q++) {
        const float* cand = q ? &g_candHi[s * CAP] : &g_candLo[s * CAP];
        int n = min(q ? g_cntHi[s] : g_cntLo[s], CAP);
        int cumBefore = g_cum[s][q];
        int t0 = (q ? KH : KL) - cumBefore;
        int t1 = t0 + 1;

        for (int i = threadIdx.x; i < n; i += 256) sv[i] = cand[i];
        __syncthreads();

        for (int i = threadIdx.x; i < n; i += 256) {
            float v = sv[i];
            int L = 0, E = 0;
            for (int j = 0; j < n; j++) {
                float u = sv[j];
                L += (u < v);
                E += (u == v);
            }
            if (L <= t0 && t0 < L + E) res[2 * q + 0] = v;
            if (L <= t1 && t1 < L + E) res[2 * q + 1] = v;
        }
        __syncthreads();
    }

    if (threadIdx.x == 0) {
        float lo = 0.5f * (res[0] + res[1]);
        float hi = 0.5f * (res[2] + res[3]);
        float rng = fmaxf(hi - lo, 1e-6f);
        g_lo[s]  = lo;
        g_inv[s] = 1.0f / rng;
        // self-clean counters for next graph replay
        g_cntLo[s] = 0;
        g_cntHi[s] = 0;
    }
}

// ---------------- pass E: normalize + clip ----------------
__global__ void __launch_bounds__(TPB_C) passE(float* __restrict__ out) {
    int s     = blockIdx.x / BPS_C;
    int chunk = blockIdx.x % BPS_C;
    float lo  = g_lo[s];
    float inv = g_inv[s];

    int base = s * HW + chunk * PXB_C + threadIdx.x * 4;
    const float4* __restrict__ xg4 = (const float4*)g_xg;
    float4* __restrict__ o4 = (float4*)out;

#pragma unroll
    for (int it = 0; it < ITER_C; ++it) {
        int e = (base + it * (TPB_C * 4)) >> 2;
        float4 v = __ldcs(xg4 + e);       // last use of xg: evict
        float4 r;
        r.x = __saturatef((v.x - lo) * inv);
        r.y = __saturatef((v.y - lo) * inv);
        r.z = __saturatef((v.z - lo) * inv);
        r.w = __saturatef((v.w - lo) * inv);
        __stcs(o4 + e, r);                // streaming store
    }
}

// ---------------- launch ----------------
extern "C" void kernel_launch(void* const* d_in, const int* in_sizes, int n_in,
                              void* d_out, int out_size) {
    const float* x = (const float*)d_in[0];
    float* out = (float*)d_out;

    passA<<<BATCH * BPS_A, TPB_A>>>(x);
    passB<<<BATCH, 256>>>();
    passC<<<BATCH * BPS_C, TPB_C>>>();
    passD<<<BATCH, 256>>>();
    passE<<<BATCH * BPS_C, TPB_C>>>(out);
}

// round 3
// speedup vs baseline: 1.7951x; 1.0774x over previous
#include <cuda_runtime.h>
#include <cstdint>

// ---------------- problem constants ----------------
#define BATCH 256
#define HW    147456           // 384*384
#define NB    4096             // histogram bins
#define CAP2  3072             // in-smem candidate capacity per quantile

// target order-statistic ranks (0-based): q*(n-1) = 14745.5 / 132709.5
#define KL  14745
#define KH  132709

// passA geometry: 4 blocks/sample, 1024 threads, 36 px/thread
#define TPB_A  1024
#define BPS_A  4
#define PXB_A  (HW / BPS_A)          // 36864 px per block
#define ITER_A (PXB_A / (TPB_A*4))   // 9 iterations of 4 px

// passE geometry: 36 blocks/sample, 512 threads, 8 px/thread
#define TPB_E  512
#define BPS_E  36
#define PXB_E  (HW / BPS_E)          // 4096 px per block
#define ITER_E (PXB_E / (TPB_E*4))   // 2 iterations of 4 px

// ---------------- device scratch (static, allocation-free, zero-init) -------
__device__ float g_xg[BATCH * HW];   // channel-mean image, 151 MB
__device__ int   g_hist[BATCH * NB]; // per-sample histograms (self-cleaned by passB)
__device__ float g_thr[BATCH][4];    // loT0, loT1, hiT0, hiT1 (t = v*4096 units)
__device__ int   g_cum[BATCH][2];    // exclusive counts before lo/hi target bins
__device__ float g_lo[BATCH];
__device__ float g_inv[BATCH];

// ---------------- pass A: xg = mean_c(x), write xg, histogram ----------------
__global__ void __launch_bounds__(TPB_A) passA(const float* __restrict__ x) {
    __shared__ int sh[NB];
    int s     = blockIdx.x >> 2;        // / BPS_A
    int chunk = blockIdx.x & (BPS_A - 1);

    for (int i = threadIdx.x; i < NB; i += TPB_A) sh[i] = 0;
    __syncthreads();

    const int base = s * HW + chunk * PXB_A;
    const float4* __restrict__ xin = (const float4*)x;
    const float third = 1.0f / 3.0f;

#pragma unroll 3
    for (int it = 0; it < ITER_A; ++it) {
        int p  = base + it * (TPB_A * 4) + threadIdx.x * 4;  // global px (mult of 4)
        int f4 = (p * 3) >> 2;
        float4 a = __ldcs(xin + f4 + 0);   // stream x: don't pollute L2
        float4 b = __ldcs(xin + f4 + 1);
        float4 c = __ldcs(xin + f4 + 2);

        float m0 = (a.x + a.y + a.z) * third;
        float m1 = (a.w + b.x + b.y) * third;
        float m2 = (b.z + b.w + c.x) * third;
        float m3 = (c.y + c.z + c.w) * third;

        float4 o; o.x = m0; o.y = m1; o.z = m2; o.w = m3;
        ((float4*)g_xg)[p >> 2] = o;       // default store: retain in L2

        atomicAdd(&sh[min((int)(m0 * (float)NB), NB - 1)], 1);
        atomicAdd(&sh[min((int)(m1 * (float)NB), NB - 1)], 1);
        atomicAdd(&sh[min((int)(m2 * (float)NB), NB - 1)], 1);
        atomicAdd(&sh[min((int)(m3 * (float)NB), NB - 1)], 1);
    }
    __syncthreads();

    int* gh = &g_hist[s * NB];
    for (int i = threadIdx.x; i < NB; i += TPB_A) {
        int v = sh[i];
        if (v) atomicAdd(&gh[i], v);   // result unused -> REDG
    }
}

// ---------------- pass B: locate ranks, export value thresholds, zero hist ----
__global__ void __launch_bounds__(256) passB() {
    int s = blockIdx.x;
    int t = threadIdx.x;
    const int CH = NB / 256;  // 16 bins per thread
    __shared__ int scan[256];
    __shared__ int selBin[4];
    __shared__ int selCum[4];

    int cnt[CH];
    int local = 0;
    int* gh = &g_hist[s * NB];
    int base = t * CH;
#pragma unroll
    for (int i = 0; i < CH; i++) { cnt[i] = gh[base + i]; local += cnt[i]; }
#pragma unroll
    for (int i = 0; i < CH; i++) gh[base + i] = 0;   // self-clean for graph replay

    scan[t] = local;
    __syncthreads();
    for (int off = 1; off < 256; off <<= 1) {
        int v = (t >= off) ? scan[t - off] : 0;
        __syncthreads();
        scan[t] += v;
        __syncthreads();
    }
    int cum = scan[t] - local;

    const int targets[4] = {KL, KL + 1, KH, KH + 1};
#pragma unroll
    for (int i = 0; i < CH; i++) {
        int c = cnt[i];
#pragma unroll
        for (int k = 0; k < 4; k++) {
            int r = targets[k];
            if (cum <= r && r < cum + c) { selBin[k] = base + i; selCum[k] = cum; }
        }
        cum += c;
    }
    __syncthreads();

    if (t == 0) {
        int loMin = selBin[0], loMax = selBin[1];
        int hiMin = selBin[2], hiMax = selBin[3];
        g_thr[s][0] = (float)loMin;
        g_thr[s][1] = (loMax == NB - 1) ? 3.0e38f : (float)(loMax + 1);
        g_thr[s][2] = (float)hiMin;
        g_thr[s][3] = (hiMax == NB - 1) ? 3.0e38f : (float)(hiMax + 1);
        g_cum[s][0] = selCum[0];
        g_cum[s][1] = selCum[2];
    }
}

// ------ pass CD (fused): gather candidates to smem + exact select in-block ---
__global__ void __launch_bounds__(1024) passCD() {
    int s = blockIdx.x;
    __shared__ float candLo[CAP2];
    __shared__ float candHi[CAP2];
    __shared__ int cLo, cHi;
    __shared__ float res[4];

    if (threadIdx.x == 0) { cLo = 0; cHi = 0; }
    __syncthreads();

    float l0 = g_thr[s][0], l1 = g_thr[s][1];
    float h0 = g_thr[s][2], h1 = g_thr[s][3];

    const float4* __restrict__ xg4 = (const float4*)(g_xg + s * HW);

#pragma unroll 4
    for (int i = threadIdx.x; i < HW / 4; i += 1024) {
        float4 v = xg4[i];
        float m[4] = {v.x, v.y, v.z, v.w};
#pragma unroll
        for (int k = 0; k < 4; k++) {
            float tt = m[k] * (float)NB;
            if (tt >= l0 && tt < l1) {
                int idx = atomicAdd(&cLo, 1);
                if (idx < CAP2) candLo[idx] = m[k];
            }
            if (tt >= h0 && tt < h1) {
                int idx = atomicAdd(&cHi, 1);
                if (idx < CAP2) candHi[idx] = m[k];
            }
        }
    }
    __syncthreads();

    // exact selection (counting rank) within candidate sets
    for (int q = 0; q < 2; q++) {
        const float* sv = q ? candHi : candLo;
        int n = min(q ? cHi : cLo, CAP2);
        int t0 = (q ? KH : KL) - g_cum[s][q];
        int t1 = t0 + 1;

        for (int i = threadIdx.x; i < n; i += 1024) {
            float v = sv[i];
            int L = 0, E = 0;
            for (int j = 0; j < n; j++) {
                float u = sv[j];
                L += (u < v);
                E += (u == v);
            }
            if (L <= t0 && t0 < L + E) res[2 * q + 0] = v;
            if (L <= t1 && t1 < L + E) res[2 * q + 1] = v;
        }
    }
    __syncthreads();

    if (threadIdx.x == 0) {
        float lo = 0.5f * (res[0] + res[1]);
        float hi = 0.5f * (res[2] + res[3]);
        float rng = fmaxf(hi - lo, 1e-6f);
        g_lo[s]  = lo;
        g_inv[s] = 1.0f / rng;
    }
}

// ---------------- pass E: normalize + clip ----------------
__global__ void __launch_bounds__(TPB_E) passE(float* __restrict__ out) {
    int s     = blockIdx.x / BPS_E;
    int chunk = blockIdx.x % BPS_E;
    float lo  = g_lo[s];
    float inv = g_inv[s];

    int base = s * HW + chunk * PXB_E + threadIdx.x * 4;
    const float4* __restrict__ xg4 = (const float4*)g_xg;
    float4* __restrict__ o4 = (float4*)out;

#pragma unroll
    for (int it = 0; it < ITER_E; ++it) {
        int e = (base + it * (TPB_E * 4)) >> 2;
        float4 v = __ldcs(xg4 + e);       // last use of xg: evict-first
        float4 r;
        r.x = __saturatef((v.x - lo) * inv);
        r.y = __saturatef((v.y - lo) * inv);
        r.z = __saturatef((v.z - lo) * inv);
        r.w = __saturatef((v.w - lo) * inv);
        __stcs(o4 + e, r);                // streaming store
    }
}

// ---------------- launch ----------------
extern "C" void kernel_launch(void* const* d_in, const int* in_sizes, int n_in,
                              void* d_out, int out_size) {
    const float* x = (const float*)d_in[0];
    float* out = (float*)d_out;

    passA<<<BATCH * BPS_A, TPB_A>>>(x);
    passB<<<BATCH, 256>>>();
    passCD<<<BATCH, 1024>>>();
    passE<<<BATCH * BPS_E, TPB_E>>>(out);
}

// round 4
// speedup vs baseline: 1.8324x; 1.0208x over previous
#include <cuda_runtime.h>
#include <cstdint>

// ---------------- problem constants ----------------
#define BATCH 256
#define HW    147456           // 384*384
#define NB    4096             // histogram bins
#define CAP2  3072             // in-smem candidate capacity per quantile

// target order-statistic ranks (0-based): q*(n-1) = 14745.5 / 132709.5
#define KL  14745
#define KH  132709

// passA geometry: 4 blocks/sample, 1024 threads, 36 px/thread
#define TPB_A  1024
#define BPS_A  4
#define PXB_A  (HW / BPS_A)          // 36864 px per block
#define ITER_A (PXB_A / (TPB_A*4))   // 9 iterations of 4 px

// ---------------- device scratch (static, allocation-free, zero-init) -------
__device__ float g_xg[BATCH * HW];   // channel-mean image, 151 MB
__device__ int   g_hist[BATCH * NB]; // per-sample histograms (self-cleaned)

// ---------------- pass A: xg = mean_c(x), write xg, histogram ----------------
__global__ void __launch_bounds__(TPB_A) passA(const float* __restrict__ x) {
    __shared__ int sh[NB];
    int s     = blockIdx.x >> 2;        // / BPS_A
    int chunk = blockIdx.x & (BPS_A - 1);

    for (int i = threadIdx.x; i < NB; i += TPB_A) sh[i] = 0;
    __syncthreads();

    const int base = s * HW + chunk * PXB_A;
    const float4* __restrict__ xin = (const float4*)x;
    const float third = 1.0f / 3.0f;

#pragma unroll 3
    for (int it = 0; it < ITER_A; ++it) {
        int p  = base + it * (TPB_A * 4) + threadIdx.x * 4;  // global px (mult of 4)
        int f4 = (p * 3) >> 2;
        float4 a = __ldcs(xin + f4 + 0);   // stream x: don't pollute L2
        float4 b = __ldcs(xin + f4 + 1);
        float4 c = __ldcs(xin + f4 + 2);

        float m0 = (a.x + a.y + a.z) * third;
        float m1 = (a.w + b.x + b.y) * third;
        float m2 = (b.z + b.w + c.x) * third;
        float m3 = (c.y + c.z + c.w) * third;

        float4 o; o.x = m0; o.y = m1; o.z = m2; o.w = m3;
        ((float4*)g_xg)[p >> 2] = o;       // default store: retain in L2

        atomicAdd(&sh[min((int)(m0 * (float)NB), NB - 1)], 1);
        atomicAdd(&sh[min((int)(m1 * (float)NB), NB - 1)], 1);
        atomicAdd(&sh[min((int)(m2 * (float)NB), NB - 1)], 1);
        atomicAdd(&sh[min((int)(m3 * (float)NB), NB - 1)], 1);
    }
    __syncthreads();

    int* gh = &g_hist[s * NB];
    for (int i = threadIdx.x; i < NB; i += TPB_A) {
        int v = sh[i];
        if (v) atomicAdd(&gh[i], v);   // result unused -> REDG
    }
}

// ---- pass BCDE (fused): hist-scan -> gather -> select -> normalize ----------
// One block per sample. Second xg scan is L2-hot (85 MB resident working set).
__global__ void __launch_bounds__(1024) passBCDE(float* __restrict__ out) {
    const int s = blockIdx.x;
    const int t = threadIdx.x;

    __shared__ int   scan[1024];
    __shared__ float thr[4];     // l0, l1, h0, h1 (in v*NB units)
    __shared__ int   cumq[2];    // exclusive counts before lo/hi target bins
    __shared__ float candLo[CAP2];
    __shared__ float candHi[CAP2];
    __shared__ int   cLo, cHi;
    __shared__ float res[4];
    __shared__ float s_lo, s_inv;

    // ---- phase 1: histogram scan (4 bins per thread), thresholds ----
    {
        const int CH = NB / 1024;  // 4
        int* gh = &g_hist[s * NB];
        int base = t * CH;
        int cnt[CH];
        int local = 0;
#pragma unroll
        for (int i = 0; i < CH; i++) { cnt[i] = gh[base + i]; local += cnt[i]; }
#pragma unroll
        for (int i = 0; i < CH; i++) gh[base + i] = 0;   // self-clean for replay

        if (t == 0) { cLo = 0; cHi = 0; }
        scan[t] = local;
        __syncthreads();
        for (int off = 1; off < 1024; off <<= 1) {
            int v = (t >= off) ? scan[t - off] : 0;
            __syncthreads();
            scan[t] += v;
            __syncthreads();
        }
        int cum = scan[t] - local;   // exclusive prefix of this thread's chunk

        const int targets[4] = {KL, KL + 1, KH, KH + 1};
        int selBin[4] = {-1, -1, -1, -1};
        int selCum[4];
#pragma unroll
        for (int i = 0; i < CH; i++) {
            int c = cnt[i];
#pragma unroll
            for (int k = 0; k < 4; k++) {
                int r = targets[k];
                if (cum <= r && r < cum + c) { selBin[k] = base + i; selCum[k] = cum; }
            }
            cum += c;
        }
        // winners publish (at most one thread per target)
#pragma unroll
        for (int k = 0; k < 4; k++) {
            if (selBin[k] >= 0) {
                if (k == 0) { thr[0] = (float)selBin[0]; cumq[0] = selCum[0]; }
                if (k == 1) { thr[1] = (selBin[1] == NB - 1) ? 3.0e38f : (float)(selBin[1] + 1); }
                if (k == 2) { thr[2] = (float)selBin[2]; cumq[1] = selCum[2]; }
                if (k == 3) { thr[3] = (selBin[3] == NB - 1) ? 3.0e38f : (float)(selBin[3] + 1); }
            }
        }
        __syncthreads();
    }

    const float l0 = thr[0], l1 = thr[1], h0 = thr[2], h1 = thr[3];
    const float4* __restrict__ xg4 = (const float4*)(g_xg + s * HW);

    // ---- phase 2: gather candidates into shared memory ----
#pragma unroll 4
    for (int i = t; i < HW / 4; i += 1024) {
        float4 v = xg4[i];
        float m[4] = {v.x, v.y, v.z, v.w};
#pragma unroll
        for (int k = 0; k < 4; k++) {
            float tt = m[k] * (float)NB;
            if (tt >= l0 && tt < l1) {
                int idx = atomicAdd(&cLo, 1);
                if (idx < CAP2) candLo[idx] = m[k];
            }
            if (tt >= h0 && tt < h1) {
                int idx = atomicAdd(&cHi, 1);
                if (idx < CAP2) candHi[idx] = m[k];
            }
        }
    }
    __syncthreads();

    // ---- phase 3: exact selection (counting rank) ----
    for (int q = 0; q < 2; q++) {
        const float* sv = q ? candHi : candLo;
        int n = min(q ? cHi : cLo, CAP2);
        int t0 = (q ? KH : KL) - cumq[q];
        int t1 = t0 + 1;

        for (int i = t; i < n; i += 1024) {
            float v = sv[i];
            int L = 0, E = 0;
            for (int j = 0; j < n; j++) {
                float u = sv[j];
                L += (u < v);
                E += (u == v);
            }
            if (L <= t0 && t0 < L + E) res[2 * q + 0] = v;
            if (L <= t1 && t1 < L + E) res[2 * q + 1] = v;
        }
    }
    __syncthreads();

    if (t == 0) {
        float lo = 0.5f * (res[0] + res[1]);
        float hi = 0.5f * (res[2] + res[3]);
        float rng = fmaxf(hi - lo, 1e-6f);
        s_lo  = lo;
        s_inv = 1.0f / rng;
    }
    __syncthreads();

    // ---- phase 4: normalize + clip (xg re-read is L2-hot) ----
    const float lo  = s_lo;
    const float inv = s_inv;
    float4* __restrict__ o4 = (float4*)(out + s * HW);

#pragma unroll 4
    for (int i = t; i < HW / 4; i += 1024) {
        float4 v = __ldcs(xg4 + i);     // last use: evict-first
        float4 r;
        r.x = __saturatef((v.x - lo) * inv);
        r.y = __saturatef((v.y - lo) * inv);
        r.z = __saturatef((v.z - lo) * inv);
        r.w = __saturatef((v.w - lo) * inv);
        __stcs(o4 + i, r);              // streaming store
    }
}

// ---------------- launch ----------------
extern "C" void kernel_launch(void* const* d_in, const int* in_sizes, int n_in,
                              void* d_out, int out_size) {
    const float* x = (const float*)d_in[0];
    float* out = (float*)d_out;

    passA<<<BATCH * BPS_A, TPB_A>>>(x);
    passBCDE<<<BATCH, 1024>>>(out);
}